// round 12
// baseline (speedup 1.0000x reference)
#include <cuda_runtime.h>
#include <cuda_bf16.h>
#include <cstdint>

typedef __nv_bfloat16 bf16;
#define DEVFN __device__ __forceinline__

// sm_103 (no 'a') toolchain: no tcgen05; bf16 mma.sync (HMMA) + cp.async path.
// R7: s8 IMMA slow. R8: fattn work-limited. R10: LUT replication + 2CTA/SM win.
// R11: GEMM is LDS-crossbar bound -> 64x64 warp tiles (4 warps) cut LDS 33%.

// ---------------- problem dims ----------------
#define Bv   4
#define Nv   1024
#define Cv   1024
#define Hv   16
#define Dv   64
#define HIDv 4096
#define Tv   (Bv*Nv)
#define BH   (Bv*Hv)

// ---------------- quantizers ----------------
DEVFN float qz4(float x){ float r = rintf(x*16.0f);  r = fminf(fmaxf(r,-128.0f),127.0f); return r*0.0625f; }
DEVFN float qz7(float x){ float r = rintf(x*128.0f); r = fminf(fmaxf(r,-128.0f),127.0f); return r*0.0078125f; }

// ---------------- device scratch ----------------
__device__ __align__(128) bf16 g_wqkv[3*Cv*Cv];
__device__ __align__(128) bf16 g_wpr [Cv*Cv];
__device__ __align__(128) bf16 g_wf1 [HIDv*Cv];
__device__ __align__(128) bf16 g_wf2 [Cv*HIDv];
__device__ __align__(128) bf16 g_h1  [Tv*Cv];
__device__ __align__(128) bf16 g_qb  [BH*Nv*Dv];     // Q pre-scaled x2 (exact)
__device__ __align__(128) bf16 g_kb  [BH*Nv*Dv];
__device__ __align__(128) bf16 g_vb  [BH*Nv*Dv];
__device__ __align__(128) bf16 g_z2  [Tv*Cv];
__device__ __align__(128) float g_x1 [Tv*Cv];
__device__ __align__(128) bf16 g_h2  [Tv*Cv];
__device__ __align__(128) bf16 g_m   [Tv*HIDv];
__device__ __align__(128) uint8_t g_sidx[(size_t)BH*Nv*Nv];   // 64MB logit-index bytes

// ---------------- PTX helpers ----------------
DEVFN uint32_t s2u(const void* p){
    uint32_t a;
    asm("{ .reg .u64 t; cvta.to.shared.u64 t, %1; cvt.u32.u64 %0, t; }" : "=r"(a) : "l"(p));
    return a;
}
DEVFN void cpasync16(uint32_t d, const void* s){
    asm volatile("cp.async.cg.shared.global [%0], [%1], 16;" :: "r"(d), "l"(s));
}
DEVFN void cpcommit(){ asm volatile("cp.async.commit_group;" ::: "memory"); }
template<int N> DEVFN void cpwait(){ asm volatile("cp.async.wait_group %0;" :: "n"(N) : "memory"); }
DEVFN void ldsm4(uint32_t* r, uint32_t addr){
    asm volatile("ldmatrix.sync.aligned.m8n8.x4.shared.b16 {%0,%1,%2,%3}, [%4];"
        : "=r"(r[0]), "=r"(r[1]), "=r"(r[2]), "=r"(r[3]) : "r"(addr));
}
DEVFN void ldsm4t(uint32_t* r, uint32_t addr){
    asm volatile("ldmatrix.sync.aligned.m8n8.x4.trans.shared.b16 {%0,%1,%2,%3}, [%4];"
        : "=r"(r[0]), "=r"(r[1]), "=r"(r[2]), "=r"(r[3]) : "r"(addr));
}
DEVFN void mma16816(float* c, const uint32_t* a, const uint32_t* b){
    asm volatile("mma.sync.aligned.m16n8k16.row.col.f32.bf16.bf16.f32 "
        "{%0,%1,%2,%3}, {%4,%5,%6,%7}, {%8,%9}, {%0,%1,%2,%3};"
        : "+f"(c[0]), "+f"(c[1]), "+f"(c[2]), "+f"(c[3])
        : "r"(a[0]), "r"(a[1]), "r"(a[2]), "r"(a[3]), "r"(b[0]), "r"(b[1]));
}
DEVFN void st_bf2(bf16* p, float a, float b){
    __nv_bfloat162 t = __halves2bfloat162(__float2bfloat16(a), __float2bfloat16(b));
    *reinterpret_cast<__nv_bfloat162*>(p) = t;
}
DEVFN uint32_t bf2pack(float hi, float lo){   // {lo, hi<<16} as bf16x2
    uint32_t r;
    asm("cvt.rn.bf16x2.f32 %0, %1, %2;" : "=r"(r) : "f"(hi), "f"(lo));
    return r;
}
DEVFN uint32_t swz(uint32_t r, uint32_t c16){ return (r<<7) + ((c16 ^ (r&7))<<4); }
DEVFN int clamp255(float f){ int i = __float2int_rn(f); return min(255, max(0, i)); }

// ---------------- epilogue functors ----------------
struct EpiQKV {
    bf16* q; bf16* k; bf16* v;
    DEVFN void operator()(int row, int col, float v0, float v1) const {
        int b=row>>10, n=row&1023;
        int sel=col>>10, rem=col&1023, h=rem>>6, d=rem&63;
        bf16* dst = (sel==0 ? q : (sel==1 ? k : v)) + (((long)(b*Hv+h))*Nv + n)*Dv + d;
        float sc = (sel==0) ? 2.0f : 1.0f;      // Q pre-scaled x2 (exact in bf16)
        st_bf2(dst, qz4(v0)*sc, qz4(v1)*sc);
    }
};
struct EpiProj {
    const float* x; const float* pb; const float* aw2; const float* ab2;
    float* x1; bf16* h2;
    DEVFN void operator()(int row, int col, float v0, float v1) const {
        float a = qz4(aw2[0]), bb = qz4(ab2[0]);
        float2 xv = *(const float2*)(x + (long)row*Cv + col);
        float2 pv = *(const float2*)(pb + col);
        float y0 = v0 + qz7(pv.x),  y1 = v1 + qz7(pv.y);
        float o0 = qz4(xv.x) + qz4(y0), o1 = qz4(xv.y) + qz4(y1);
        *(float2*)(x1 + (long)row*Cv + col) = make_float2(o0, o1);
        float h0 = qz4(qz4(qz4(o0)*a) + bb);
        float h1 = qz4(qz4(qz4(o1)*a) + bb);
        st_bf2(h2 + (long)row*Cv + col, h0, h1);
    }
};
struct EpiFc1 {
    const float* b1; bf16* m;
    DEVFN void operator()(int row, int col, float v0, float v1) const {
        float2 bv = *(const float2*)(b1 + col);
        float y0 = fmaxf(v0 + qz7(bv.x), 0.f);
        float y1 = fmaxf(v1 + qz7(bv.y), 0.f);
        st_bf2(m + (long)row*HIDv + col, qz4(y0), qz4(y1));
    }
};
struct EpiFc2 {
    const float* b2; const float* x1; float* out;
    DEVFN void operator()(int row, int col, float v0, float v1) const {
        float2 bv = *(const float2*)(b2 + col);
        float2 xv = *(const float2*)(x1 + (long)row*Cv + col);
        float y0 = v0 + qz7(bv.x), y1 = v1 + qz7(bv.y);
        *(float2*)(out + (long)row*Cv + col) =
            make_float2(qz4(xv.x) + qz4(y0), qz4(xv.y) + qz4(y1));
    }
};

// ---------------- GEMM: C[128x128] = A @ B^T, 4 warps x 64x64 tiles, BK=64, 3-stage ----
constexpr int TILE = 128*128;        // 16 KB
constexpr int GSTG = 2*TILE;
constexpr int GSM  = 3*GSTG;         // 96 KB

template<class Epi>
__global__ void __launch_bounds__(128,2)
gemm_mma(const bf16* __restrict__ A, const bf16* __restrict__ Bm, int K, Epi epi)
{
    extern __shared__ char dsm[];
    uint32_t base = s2u(dsm);
    int tid = threadIdx.x, wid = tid>>5, lane = tid&31;
    int wm = wid & 1, wn = wid >> 1;          // 2 x 2 warps, each 64x64
    int m0 = blockIdx.y*128, n0 = blockIdx.x*128;
    const bf16* Ab = A + (long)m0*K;
    const bf16* Bb = Bm + (long)n0*K;
    const int KC = K >> 6;

    auto load = [&](int ch, int st){
        uint32_t ab = base + st*GSTG, bb = ab + TILE;
        const bf16* Ac = Ab + ch*64;
        const bf16* Bc = Bb + ch*64;
        #pragma unroll
        for(int j=0;j<8;j++){
            int i = tid + j*128; int r = i>>3, c = i&7;
            cpasync16(ab + swz(r,c), Ac + (long)r*K + c*8);
            cpasync16(bb + swz(r,c), Bc + (long)r*K + c*8);
        }
        cpcommit();
    };

    float acc[4][8][4];
    #pragma unroll
    for(int mb=0;mb<4;mb++)
        #pragma unroll
        for(int j=0;j<8;j++)
            #pragma unroll
            for(int u=0;u<4;u++) acc[mb][j][u]=0.f;

    load(0,0);
    load(1,1);
    int t = lane>>3, lr = lane&7;
    int rAdd = (t&1)*8 + lr, cAdd = (t>>1)*8;

    for(int c=0;c<KC;c++){
        if (c+1 < KC) cpwait<1>(); else cpwait<0>();
        __syncthreads();
        if (c+2 < KC) load(c+2, (c+2)%3);
        uint32_t ab = base + (c%3)*GSTG, bb = ab + TILE;
        #pragma unroll
        for(int kk=0; kk<64; kk+=16){
            int ch = (kk + cAdd)>>3;
            uint32_t afr[4][4];
            #pragma unroll
            for(int mb=0;mb<4;mb++){
                int row = wm*64 + mb*16 + rAdd;
                ldsm4(afr[mb], ab + (row<<7) + ((ch ^ (row&7))<<4));
            }
            #pragma unroll
            for(int g=0; g<4; g++){
                int row = wn*64 + g*16 + rAdd;
                uint32_t r4[4];
                ldsm4(r4, bb + (row<<7) + ((ch ^ (row&7))<<4));
                uint32_t b0[2]={r4[0],r4[2]}, b1[2]={r4[1],r4[3]};
                #pragma unroll
                for(int mb=0;mb<4;mb++){
                    mma16816(acc[mb][2*g],   afr[mb], b0);
                    mma16816(acc[mb][2*g+1], afr[mb], b1);
                }
            }
        }
    }

    int colB = n0 + wn*64 + (lane&3)*2;
    #pragma unroll
    for(int mb=0;mb<4;mb++){
        int row0 = m0 + wm*64 + mb*16 + (lane>>2);
        #pragma unroll
        for(int j=0;j<8;j++){
            int cc = colB + j*8;
            epi(row0,   cc, acc[mb][j][0], acc[mb][j][1]);
            epi(row0+8, cc, acc[mb][j][2], acc[mb][j][3]);
        }
    }
}

// ---------------- fused attention v3 (R10 winner, unchanged) ----------------
constexpr int FA_Q   = 32768;
constexpr int FA_KV0 = FA_Q  + TILE;
constexpr int FA_KV1 = FA_KV0 + TILE;
constexpr int FA_SM  = FA_KV1 + TILE;       // 81920

__global__ void __launch_bounds__(256,2)
fattn_k(const bf16* __restrict__ q, const bf16* __restrict__ k,
        const bf16* __restrict__ v, bf16* __restrict__ z2, uint8_t* __restrict__ sidx)
{
    extern __shared__ char dsm[];
    float* lutE = (float*)dsm;
    uint32_t base = s2u(dsm);
    uint32_t qs = base + FA_Q;
    uint32_t kv[2] = {base+FA_KV0, base+FA_KV1};

    int tid = threadIdx.x, wid = tid>>5, lane = tid&31;
    int bh = blockIdx.y, b = bh>>4, h = bh&15;
    int q0 = blockIdx.x*128;
    const bf16* Qb = q + ((long)bh*Nv + q0)*Dv;
    const bf16* Kb = k + (long)bh*Nv*Dv;
    const bf16* Vb = v + (long)bh*Nv*Dv;
    uint8_t* sA = sidx + ((long)(bh*8 + blockIdx.x))*131072 + wid*2048 + lane*8;

    {
        float ev = expf((float)(tid-128)*0.0625f - 7.9375f);
        #pragma unroll
        for(int j=0;j<32;j++){
            float vj = __shfl_sync(0xffffffffu, ev, j);
            lutE[(wid*32 + j)*32 + lane] = vj;
        }
    }
    const float* eb = lutE + lane;

    #pragma unroll
    for(int j=0;j<4;j++){
        int i = tid + j*256; int r = i>>3, c = i&7;
        cpasync16(qs + swz(r,c), Qb + (long)r*Dv + c*8);
    }
    cpcommit();

    int t = lane>>3, lr = lane&7;
    int rAdd = (t&1)*8 + lr, cAdd = (t>>1)*8;

    auto loadT = [&](const bf16* src, int st){
        #pragma unroll
        for(int j=0;j<4;j++){
            int i = tid + j*256; int r = i>>3, cc = i&7;
            cpasync16(kv[st] + swz(r,cc), src + (long)r*Dv + cc*8);
        }
        cpcommit();
    };

    loadT(Kb, 0);
    cpwait<0>(); __syncthreads();

    uint32_t qf[4][4];
    #pragma unroll
    for(int kk=0;kk<4;kk++){
        int row = wid*16 + rAdd;
        int ch = (kk*16 + cAdd)>>3;
        ldsm4(qf[kk], qs + (row<<7) + ((ch ^ (row&7))<<4));
    }

    auto computeS2 = [&](uint32_t kb_, int kg, float s2[2][4]){
        #pragma unroll
        for(int u=0;u<4;u++){ s2[0][u]=128.0f; s2[1][u]=128.0f; }
        #pragma unroll
        for(int kk=0;kk<4;kk++){
            int row = kg*16 + rAdd;
            int ch = (kk*16 + cAdd)>>3;
            uint32_t r4[4];
            ldsm4(r4, kb_ + (row<<7) + ((ch ^ (row&7))<<4));
            uint32_t b0[2]={r4[0],r4[2]}, b1[2]={r4[1],r4[3]};
            mma16816(s2[0], qf[kk], b0);
            mma16816(s2[1], qf[kk], b1);
        }
    };

    float rs0 = 0.f, rs1 = 0.f;
    for(int c=0;c<8;c++){
        cpwait<0>(); __syncthreads();
        if (c<7) loadT(Kb + (long)((c+1)*128)*Dv, (c+1)&1);
        #pragma unroll
        for(int kg=0;kg<8;kg++){
            float s2[2][4];
            computeS2(kv[c&1], kg, s2);
            int u00=clamp255(s2[0][0]), u01=clamp255(s2[0][1]), u02=clamp255(s2[0][2]), u03=clamp255(s2[0][3]);
            int u10=clamp255(s2[1][0]), u11=clamp255(s2[1][1]), u12=clamp255(s2[1][2]), u13=clamp255(s2[1][3]);
            rs0 += eb[u00*32] + eb[u01*32] + eb[u10*32] + eb[u11*32];
            rs1 += eb[u02*32] + eb[u03*32] + eb[u12*32] + eb[u13*32];
            uint32_t w0 = (uint32_t)u00 | ((uint32_t)u01<<8) | ((uint32_t)u10<<16) | ((uint32_t)u11<<24);
            uint32_t w1 = (uint32_t)u02 | ((uint32_t)u03<<8) | ((uint32_t)u12<<16) | ((uint32_t)u13<<24);
            *reinterpret_cast<uint2*>(sA + c*16384 + kg*256) = make_uint2(w0, w1);
        }
    }
    rs0 += __shfl_xor_sync(0xffffffffu, rs0, 1);
    rs0 += __shfl_xor_sync(0xffffffffu, rs0, 2);
    rs1 += __shfl_xor_sync(0xffffffffu, rs1, 1);
    rs1 += __shfl_xor_sync(0xffffffffu, rs1, 2);
    float iv0 = 128.0f/rs0, iv1 = 128.0f/rs1;

    auto P = [&](uint32_t byte, float iv)->float{
        float e = eb[byte*32];
        return fminf(rintf(e*iv), 127.f) * 0.0078125f;
    };

    float oacc[8][4];
    #pragma unroll
    for(int j=0;j<8;j++){ oacc[j][0]=0.f; oacc[j][1]=0.f; oacc[j][2]=0.f; oacc[j][3]=0.f; }

    loadT(Vb, 0);
    for(int c=0;c<8;c++){
        uint2 w[8];
        #pragma unroll
        for(int kg=0;kg<8;kg++)
            w[kg] = *reinterpret_cast<const uint2*>(sA + c*16384 + kg*256);
        cpwait<0>(); __syncthreads();
        if (c<7) loadT(Vb + (long)((c+1)*128)*Dv, (c+1)&1);
        #pragma unroll
        for(int kg=0;kg<8;kg++){
            uint32_t w0 = w[kg].x, w1 = w[kg].y;
            uint32_t pa[4];
            pa[0] = bf2pack(P((w0>>8)&255u, iv0), P(w0&255u, iv0));
            pa[1] = bf2pack(P((w1>>8)&255u, iv1), P(w1&255u, iv1));
            pa[2] = bf2pack(P(w0>>24, iv0),       P((w0>>16)&255u, iv0));
            pa[3] = bf2pack(P(w1>>24, iv1),       P((w1>>16)&255u, iv1));
            #pragma unroll
            for(int dg=0;dg<4;dg++){
                int row = kg*16 + rAdd;
                int ch = (dg*16 + cAdd)>>3;
                uint32_t r4[4];
                ldsm4t(r4, kv[c&1] + (row<<7) + ((ch ^ (row&7))<<4));
                uint32_t b0[2]={r4[0],r4[1]}, b1[2]={r4[2],r4[3]};
                mma16816(oacc[2*dg],   pa, b0);
                mma16816(oacc[2*dg+1], pa, b1);
            }
        }
    }

    int n = q0 + wid*16 + (lane>>2);
    long ro = ((long)(b*Nv) + n)*Cv + h*Dv;
    int d0 = 2*(lane&3);
    #pragma unroll
    for(int og=0;og<8;og++){
        st_bf2(z2 + ro +        og*8 + d0, qz4(oacc[og][0]), qz4(oacc[og][1]));
        st_bf2(z2 + ro + 8*Cv + og*8 + d0, qz4(oacc[og][2]), qz4(oacc[og][3]));
    }
}

// ---------------- prep: weight quant (5 tensors) + affine1, one launch ----------------
__global__ void prep_all(const float4* qw, const float4* kvw, const float4* pw,
                         const float4* f1w, const float4* f2w, const float4* x,
                         const float* a1w, const float* a1b,
                         uint2* wqkv, uint2* wpr, uint2* wf1, uint2* wf2, uint2* h1)
{
    int bx = blockIdx.x;
    if (bx >= 12288){
        int i = (bx-12288)*256 + threadIdx.x;
        float a = qz4(a1w[0]), b = qz4(a1b[0]);
        float4 v = x[i];
        float o[4] = {v.x,v.y,v.z,v.w};
        #pragma unroll
        for(int u=0;u<4;u++){ float t = qz4(o[u])*a; o[u] = qz4(qz4(t)+b); }
        __nv_bfloat162 lo = __halves2bfloat162(__float2bfloat16(o[0]), __float2bfloat16(o[1]));
        __nv_bfloat162 hi = __halves2bfloat162(__float2bfloat16(o[2]), __float2bfloat16(o[3]));
        h1[i] = make_uint2(*(uint32_t*)&lo, *(uint32_t*)&hi);
        return;
    }
    const float4* src; uint2* dst; int li;
    if      (bx < 1024){ src=qw;  dst=wqkv;          li=bx; }
    else if (bx < 3072){ src=kvw; dst=wqkv + 262144; li=bx-1024; }
    else if (bx < 4096){ src=pw;  dst=wpr;           li=bx-3072; }
    else if (bx < 8192){ src=f1w; dst=wf1;           li=bx-4096; }
    else               { src=f2w; dst=wf2;           li=bx-8192; }
    int i = li*256 + threadIdx.x;
    float4 v = src[i];
    __nv_bfloat162 lo = __halves2bfloat162(__float2bfloat16(qz7(v.x)), __float2bfloat16(qz7(v.y)));
    __nv_bfloat162 hi = __halves2bfloat162(__float2bfloat16(qz7(v.z)), __float2bfloat16(qz7(v.w)));
    dst[i] = make_uint2(*(uint32_t*)&lo, *(uint32_t*)&hi);
}

// ---------------- host launcher ----------------
extern "C" void kernel_launch(void* const* d_in, const int* in_sizes, int n_in,
                              void* d_out, int out_size)
{
    (void)in_sizes; (void)n_in; (void)out_size;
    const float* x   = (const float*)d_in[0];
    const float* qw  = (const float*)d_in[1];
    const float* kvw = (const float*)d_in[2];
    const float* pw  = (const float*)d_in[3];
    const float* pb  = (const float*)d_in[4];
    const float* f1w = (const float*)d_in[5];
    const float* f1b = (const float*)d_in[6];
    const float* f2w = (const float*)d_in[7];
    const float* f2b = (const float*)d_in[8];
    const float* a1w = (const float*)d_in[9];
    const float* a1b = (const float*)d_in[10];
    const float* a2w = (const float*)d_in[11];
    const float* a2b = (const float*)d_in[12];
    float* out = (float*)d_out;

    bf16 *wqkv,*wpr,*wf1,*wf2,*h1,*qb,*kb,*vb,*z2,*h2,*m;
    float *x1; uint8_t *sidx;
    cudaGetSymbolAddress((void**)&wqkv,g_wqkv);
    cudaGetSymbolAddress((void**)&wpr, g_wpr);
    cudaGetSymbolAddress((void**)&wf1, g_wf1);
    cudaGetSymbolAddress((void**)&wf2, g_wf2);
    cudaGetSymbolAddress((void**)&h1,  g_h1);
    cudaGetSymbolAddress((void**)&qb,  g_qb);
    cudaGetSymbolAddress((void**)&kb,  g_kb);
    cudaGetSymbolAddress((void**)&vb,  g_vb);
    cudaGetSymbolAddress((void**)&z2,  g_z2);
    cudaGetSymbolAddress((void**)&x1,  g_x1);
    cudaGetSymbolAddress((void**)&h2,  g_h2);
    cudaGetSymbolAddress((void**)&m,   g_m);
    cudaGetSymbolAddress((void**)&sidx,g_sidx);

    cudaFuncSetAttribute(gemm_mma<EpiQKV>, cudaFuncAttributeMaxDynamicSharedMemorySize, GSM);
    cudaFuncSetAttribute(gemm_mma<EpiProj>,cudaFuncAttributeMaxDynamicSharedMemorySize, GSM);
    cudaFuncSetAttribute(gemm_mma<EpiFc1>, cudaFuncAttributeMaxDynamicSharedMemorySize, GSM);
    cudaFuncSetAttribute(gemm_mma<EpiFc2>, cudaFuncAttributeMaxDynamicSharedMemorySize, GSM);
    cudaFuncSetAttribute(fattn_k,          cudaFuncAttributeMaxDynamicSharedMemorySize, FA_SM);

    // 1) weights quant + affine1 (one launch)
    prep_all<<<16384, 256>>>((const float4*)qw, (const float4*)kvw, (const float4*)pw,
                             (const float4*)f1w, (const float4*)f2w, (const float4*)x,
                             a1w, a1b,
                             (uint2*)wqkv, (uint2*)wpr, (uint2*)wf1, (uint2*)wf2, (uint2*)h1);

    // 2) fused qkv projection (Q pre-scaled x2)
    { EpiQKV e{qb,kb,vb};
      gemm_mma<EpiQKV><<<dim3(3*Cv/128, Tv/128), 128, GSM>>>(h1, wqkv, Cv, e); }

    // 3) fused attention -> z2
    fattn_k<<<dim3(Nv/128, BH), 256, FA_SM>>>(qb, kb, vb, z2, sidx);

    // 4) proj + add1 + affine2
    { EpiProj e{x, pb, a2w, a2b, x1, h2};
      gemm_mma<EpiProj><<<dim3(Cv/128,  Tv/128), 128, GSM>>>(z2, wpr, Cv, e); }
    // 5) fc1 + relu
    { EpiFc1 e{f1b, m};
      gemm_mma<EpiFc1><<<dim3(HIDv/128, Tv/128), 128, GSM>>>(h2, wf1, Cv, e); }
    // 6) fc2 + add2 -> out
    { EpiFc2 e{f2b, x1, out};
      gemm_mma<EpiFc2><<<dim3(Cv/128,  Tv/128), 128, GSM>>>(m, wf2, HIDv, e); }
}

// round 13
// speedup vs baseline: 1.0932x; 1.0932x over previous
#include <cuda_runtime.h>
#include <cuda_bf16.h>
#include <cstdint>

typedef __nv_bfloat16 bf16;
#define DEVFN __device__ __forceinline__

// sm_103 (no 'a') toolchain: no tcgen05; bf16 mma.sync (HMMA) + cp.async path.
// R7: s8 IMMA slow. R8/R11: occupancy is register-limited (128 regs/thr for 2CTA);
// warp tile 32x64 (acc=64) is the RF sweet spot. R10: LUT replication + global idx win.
// R12: decouple ldsm from mma (load-all-then-mma-all) within the register budget.

// ---------------- problem dims ----------------
#define Bv   4
#define Nv   1024
#define Cv   1024
#define Hv   16
#define Dv   64
#define HIDv 4096
#define Tv   (Bv*Nv)
#define BH   (Bv*Hv)

// ---------------- quantizers ----------------
DEVFN float qz4(float x){ float r = rintf(x*16.0f);  r = fminf(fmaxf(r,-128.0f),127.0f); return r*0.0625f; }
DEVFN float qz7(float x){ float r = rintf(x*128.0f); r = fminf(fmaxf(r,-128.0f),127.0f); return r*0.0078125f; }

// ---------------- device scratch ----------------
__device__ __align__(128) bf16 g_wqkv[3*Cv*Cv];
__device__ __align__(128) bf16 g_wpr [Cv*Cv];
__device__ __align__(128) bf16 g_wf1 [HIDv*Cv];
__device__ __align__(128) bf16 g_wf2 [Cv*HIDv];
__device__ __align__(128) bf16 g_h1  [Tv*Cv];
__device__ __align__(128) bf16 g_qb  [BH*Nv*Dv];     // Q pre-scaled x2 (exact)
__device__ __align__(128) bf16 g_kb  [BH*Nv*Dv];
__device__ __align__(128) bf16 g_vb  [BH*Nv*Dv];
__device__ __align__(128) bf16 g_z2  [Tv*Cv];
__device__ __align__(128) float g_x1 [Tv*Cv];
__device__ __align__(128) bf16 g_h2  [Tv*Cv];
__device__ __align__(128) bf16 g_m   [Tv*HIDv];
__device__ __align__(128) uint8_t g_sidx[(size_t)BH*Nv*Nv];   // 64MB logit-index bytes

// ---------------- PTX helpers ----------------
DEVFN uint32_t s2u(const void* p){
    uint32_t a;
    asm("{ .reg .u64 t; cvta.to.shared.u64 t, %1; cvt.u32.u64 %0, t; }" : "=r"(a) : "l"(p));
    return a;
}
DEVFN void cpasync16(uint32_t d, const void* s){
    asm volatile("cp.async.cg.shared.global [%0], [%1], 16;" :: "r"(d), "l"(s));
}
DEVFN void cpcommit(){ asm volatile("cp.async.commit_group;" ::: "memory"); }
template<int N> DEVFN void cpwait(){ asm volatile("cp.async.wait_group %0;" :: "n"(N) : "memory"); }
DEVFN void ldsm4(uint32_t* r, uint32_t addr){
    asm volatile("ldmatrix.sync.aligned.m8n8.x4.shared.b16 {%0,%1,%2,%3}, [%4];"
        : "=r"(r[0]), "=r"(r[1]), "=r"(r[2]), "=r"(r[3]) : "r"(addr));
}
DEVFN void ldsm4t(uint32_t* r, uint32_t addr){
    asm volatile("ldmatrix.sync.aligned.m8n8.x4.trans.shared.b16 {%0,%1,%2,%3}, [%4];"
        : "=r"(r[0]), "=r"(r[1]), "=r"(r[2]), "=r"(r[3]) : "r"(addr));
}
DEVFN void mma16816(float* c, const uint32_t* a, const uint32_t* b){
    asm volatile("mma.sync.aligned.m16n8k16.row.col.f32.bf16.bf16.f32 "
        "{%0,%1,%2,%3}, {%4,%5,%6,%7}, {%8,%9}, {%0,%1,%2,%3};"
        : "+f"(c[0]), "+f"(c[1]), "+f"(c[2]), "+f"(c[3])
        : "r"(a[0]), "r"(a[1]), "r"(a[2]), "r"(a[3]), "r"(b[0]), "r"(b[1]));
}
DEVFN void st_bf2(bf16* p, float a, float b){
    __nv_bfloat162 t = __halves2bfloat162(__float2bfloat16(a), __float2bfloat16(b));
    *reinterpret_cast<__nv_bfloat162*>(p) = t;
}
DEVFN uint32_t bf2pack(float hi, float lo){   // {lo, hi<<16} as bf16x2
    uint32_t r;
    asm("cvt.rn.bf16x2.f32 %0, %1, %2;" : "=r"(r) : "f"(hi), "f"(lo));
    return r;
}
DEVFN uint32_t swz(uint32_t r, uint32_t c16){ return (r<<7) + ((c16 ^ (r&7))<<4); }
DEVFN int clamp255(float f){ int i = __float2int_rn(f); return min(255, max(0, i)); }

// ---------------- epilogue functors ----------------
struct EpiQKV {
    bf16* q; bf16* k; bf16* v;
    DEVFN void operator()(int row, int col, float v0, float v1) const {
        int b=row>>10, n=row&1023;
        int sel=col>>10, rem=col&1023, h=rem>>6, d=rem&63;
        bf16* dst = (sel==0 ? q : (sel==1 ? k : v)) + (((long)(b*Hv+h))*Nv + n)*Dv + d;
        float sc = (sel==0) ? 2.0f : 1.0f;      // Q pre-scaled x2 (exact in bf16)
        st_bf2(dst, qz4(v0)*sc, qz4(v1)*sc);
    }
};
struct EpiProj {
    const float* x; const float* pb; const float* aw2; const float* ab2;
    float* x1; bf16* h2;
    DEVFN void operator()(int row, int col, float v0, float v1) const {
        float a = qz4(aw2[0]), bb = qz4(ab2[0]);
        float2 xv = *(const float2*)(x + (long)row*Cv + col);
        float2 pv = *(const float2*)(pb + col);
        float y0 = v0 + qz7(pv.x),  y1 = v1 + qz7(pv.y);
        float o0 = qz4(xv.x) + qz4(y0), o1 = qz4(xv.y) + qz4(y1);
        *(float2*)(x1 + (long)row*Cv + col) = make_float2(o0, o1);
        float h0 = qz4(qz4(qz4(o0)*a) + bb);
        float h1 = qz4(qz4(qz4(o1)*a) + bb);
        st_bf2(h2 + (long)row*Cv + col, h0, h1);
    }
};
struct EpiFc1 {
    const float* b1; bf16* m;
    DEVFN void operator()(int row, int col, float v0, float v1) const {
        float2 bv = *(const float2*)(b1 + col);
        float y0 = fmaxf(v0 + qz7(bv.x), 0.f);
        float y1 = fmaxf(v1 + qz7(bv.y), 0.f);
        st_bf2(m + (long)row*HIDv + col, qz4(y0), qz4(y1));
    }
};
struct EpiFc2 {
    const float* b2; const float* x1; float* out;
    DEVFN void operator()(int row, int col, float v0, float v1) const {
        float2 bv = *(const float2*)(b2 + col);
        float2 xv = *(const float2*)(x1 + (long)row*Cv + col);
        float y0 = v0 + qz7(bv.x), y1 = v1 + qz7(bv.y);
        *(float2*)(out + (long)row*Cv + col) =
            make_float2(qz4(xv.x) + qz4(y0), qz4(xv.y) + qz4(y1));
    }
};

// ---------------- GEMM: C[128x128] = A @ B^T, 8 warps x 32x64, BK=64, 3-stage ----------
constexpr int TILE = 128*128;        // 16 KB
constexpr int GSTG = 2*TILE;
constexpr int GSM  = 3*GSTG;         // 96 KB

template<class Epi>
__global__ void __launch_bounds__(256,2)
gemm_mma(const bf16* __restrict__ A, const bf16* __restrict__ Bm, int K, Epi epi)
{
    extern __shared__ char dsm[];
    uint32_t base = s2u(dsm);
    int tid = threadIdx.x, wid = tid>>5, lane = tid&31;
    int wm = wid & 3, wn = wid >> 2;
    int m0 = blockIdx.y*128, n0 = blockIdx.x*128;
    const bf16* Ab = A + (long)m0*K;
    const bf16* Bb = Bm + (long)n0*K;
    const int KC = K >> 6;

    auto load = [&](int ch, int st){
        uint32_t ab = base + st*GSTG, bb = ab + TILE;
        const bf16* Ac = Ab + ch*64;
        const bf16* Bc = Bb + ch*64;
        #pragma unroll
        for(int j=0;j<4;j++){
            int i = tid + j*256; int r = i>>3, c = i&7;
            cpasync16(ab + swz(r,c), Ac + (long)r*K + c*8);
            cpasync16(bb + swz(r,c), Bc + (long)r*K + c*8);
        }
        cpcommit();
    };

    float acc[2][8][4];
    #pragma unroll
    for(int im=0;im<2;im++)
        #pragma unroll
        for(int j=0;j<8;j++)
            #pragma unroll
            for(int u=0;u<4;u++) acc[im][j][u]=0.f;

    load(0,0);
    load(1,1);
    int t = lane>>3, lr = lane&7;
    int rAdd = (t&1)*8 + lr, cAdd = (t>>1)*8;

    for(int c=0;c<KC;c++){
        if (c+1 < KC) cpwait<1>(); else cpwait<0>();
        __syncthreads();
        if (c+2 < KC) load(c+2, (c+2)%3);
        uint32_t ab = base + (c%3)*GSTG, bb = ab + TILE;
        #pragma unroll
        for(int kk=0; kk<64; kk+=16){
            int ch = (kk + cAdd)>>3;
            // load ALL fragments first (2 A + 4 B), then run all 16 mma:
            // breaks the ldsm->mma dependency chain; ptxas overlaps next kk's
            // ldsm with this kk's mma burst.
            uint32_t afr[2][4];
            #pragma unroll
            for(int im=0;im<2;im++){
                int row = wm*32 + im*16 + rAdd;
                ldsm4(afr[im], ab + (row<<7) + ((ch ^ (row&7))<<4));
            }
            uint32_t bfr[4][4];
            #pragma unroll
            for(int g=0; g<4; g++){
                int row = wn*64 + g*16 + rAdd;
                ldsm4(bfr[g], bb + (row<<7) + ((ch ^ (row&7))<<4));
            }
            #pragma unroll
            for(int g=0; g<4; g++){
                uint32_t b0[2]={bfr[g][0],bfr[g][2]}, b1[2]={bfr[g][1],bfr[g][3]};
                #pragma unroll
                for(int im=0;im<2;im++){
                    mma16816(acc[im][2*g],   afr[im], b0);
                    mma16816(acc[im][2*g+1], afr[im], b1);
                }
            }
        }
    }

    int row0 = m0 + wm*32 + (lane>>2);
    int col0 = n0 + wn*64 + (lane&3)*2;
    #pragma unroll
    for(int im=0;im<2;im++)
        #pragma unroll
        for(int j=0;j<8;j++){
            int r = row0 + im*16, cc = col0 + j*8;
            epi(r,   cc, acc[im][j][0], acc[im][j][1]);
            epi(r+8, cc, acc[im][j][2], acc[im][j][3]);
        }
}

// ---------------- fused attention v3 (R10 winner, unchanged) ----------------
constexpr int FA_Q   = 32768;
constexpr int FA_KV0 = FA_Q  + TILE;
constexpr int FA_KV1 = FA_KV0 + TILE;
constexpr int FA_SM  = FA_KV1 + TILE;       // 81920

__global__ void __launch_bounds__(256,2)
fattn_k(const bf16* __restrict__ q, const bf16* __restrict__ k,
        const bf16* __restrict__ v, bf16* __restrict__ z2, uint8_t* __restrict__ sidx)
{
    extern __shared__ char dsm[];
    float* lutE = (float*)dsm;
    uint32_t base = s2u(dsm);
    uint32_t qs = base + FA_Q;
    uint32_t kv[2] = {base+FA_KV0, base+FA_KV1};

    int tid = threadIdx.x, wid = tid>>5, lane = tid&31;
    int bh = blockIdx.y, b = bh>>4, h = bh&15;
    int q0 = blockIdx.x*128;
    const bf16* Qb = q + ((long)bh*Nv + q0)*Dv;
    const bf16* Kb = k + (long)bh*Nv*Dv;
    const bf16* Vb = v + (long)bh*Nv*Dv;
    uint8_t* sA = sidx + ((long)(bh*8 + blockIdx.x))*131072 + wid*2048 + lane*8;

    {
        float ev = expf((float)(tid-128)*0.0625f - 7.9375f);
        #pragma unroll
        for(int j=0;j<32;j++){
            float vj = __shfl_sync(0xffffffffu, ev, j);
            lutE[(wid*32 + j)*32 + lane] = vj;
        }
    }
    const float* eb = lutE + lane;

    #pragma unroll
    for(int j=0;j<4;j++){
        int i = tid + j*256; int r = i>>3, c = i&7;
        cpasync16(qs + swz(r,c), Qb + (long)r*Dv + c*8);
    }
    cpcommit();

    int t = lane>>3, lr = lane&7;
    int rAdd = (t&1)*8 + lr, cAdd = (t>>1)*8;

    auto loadT = [&](const bf16* src, int st){
        #pragma unroll
        for(int j=0;j<4;j++){
            int i = tid + j*256; int r = i>>3, cc = i&7;
            cpasync16(kv[st] + swz(r,cc), src + (long)r*Dv + cc*8);
        }
        cpcommit();
    };

    loadT(Kb, 0);
    cpwait<0>(); __syncthreads();

    uint32_t qf[4][4];
    #pragma unroll
    for(int kk=0;kk<4;kk++){
        int row = wid*16 + rAdd;
        int ch = (kk*16 + cAdd)>>3;
        ldsm4(qf[kk], qs + (row<<7) + ((ch ^ (row&7))<<4));
    }

    auto computeS2 = [&](uint32_t kb_, int kg, float s2[2][4]){
        #pragma unroll
        for(int u=0;u<4;u++){ s2[0][u]=128.0f; s2[1][u]=128.0f; }
        #pragma unroll
        for(int kk=0;kk<4;kk++){
            int row = kg*16 + rAdd;
            int ch = (kk*16 + cAdd)>>3;
            uint32_t r4[4];
            ldsm4(r4, kb_ + (row<<7) + ((ch ^ (row&7))<<4));
            uint32_t b0[2]={r4[0],r4[2]}, b1[2]={r4[1],r4[3]};
            mma16816(s2[0], qf[kk], b0);
            mma16816(s2[1], qf[kk], b1);
        }
    };

    float rs0 = 0.f, rs1 = 0.f;
    for(int c=0;c<8;c++){
        cpwait<0>(); __syncthreads();
        if (c<7) loadT(Kb + (long)((c+1)*128)*Dv, (c+1)&1);
        #pragma unroll
        for(int kg=0;kg<8;kg++){
            float s2[2][4];
            computeS2(kv[c&1], kg, s2);
            int u00=clamp255(s2[0][0]), u01=clamp255(s2[0][1]), u02=clamp255(s2[0][2]), u03=clamp255(s2[0][3]);
            int u10=clamp255(s2[1][0]), u11=clamp255(s2[1][1]), u12=clamp255(s2[1][2]), u13=clamp255(s2[1][3]);
            rs0 += eb[u00*32] + eb[u01*32] + eb[u10*32] + eb[u11*32];
            rs1 += eb[u02*32] + eb[u03*32] + eb[u12*32] + eb[u13*32];
            uint32_t w0 = (uint32_t)u00 | ((uint32_t)u01<<8) | ((uint32_t)u10<<16) | ((uint32_t)u11<<24);
            uint32_t w1 = (uint32_t)u02 | ((uint32_t)u03<<8) | ((uint32_t)u12<<16) | ((uint32_t)u13<<24);
            *reinterpret_cast<uint2*>(sA + c*16384 + kg*256) = make_uint2(w0, w1);
        }
    }
    rs0 += __shfl_xor_sync(0xffffffffu, rs0, 1);
    rs0 += __shfl_xor_sync(0xffffffffu, rs0, 2);
    rs1 += __shfl_xor_sync(0xffffffffu, rs1, 1);
    rs1 += __shfl_xor_sync(0xffffffffu, rs1, 2);
    float iv0 = 128.0f/rs0, iv1 = 128.0f/rs1;

    auto P = [&](uint32_t byte, float iv)->float{
        float e = eb[byte*32];
        return fminf(rintf(e*iv), 127.f) * 0.0078125f;
    };

    float oacc[8][4];
    #pragma unroll
    for(int j=0;j<8;j++){ oacc[j][0]=0.f; oacc[j][1]=0.f; oacc[j][2]=0.f; oacc[j][3]=0.f; }

    loadT(Vb, 0);
    for(int c=0;c<8;c++){
        uint2 w[8];
        #pragma unroll
        for(int kg=0;kg<8;kg++)
            w[kg] = *reinterpret_cast<const uint2*>(sA + c*16384 + kg*256);
        cpwait<0>(); __syncthreads();
        if (c<7) loadT(Vb + (long)((c+1)*128)*Dv, (c+1)&1);
        #pragma unroll
        for(int kg=0;kg<8;kg++){
            uint32_t w0 = w[kg].x, w1 = w[kg].y;
            uint32_t pa[4];
            pa[0] = bf2pack(P((w0>>8)&255u, iv0), P(w0&255u, iv0));
            pa[1] = bf2pack(P((w1>>8)&255u, iv1), P(w1&255u, iv1));
            pa[2] = bf2pack(P(w0>>24, iv0),       P((w0>>16)&255u, iv0));
            pa[3] = bf2pack(P(w1>>24, iv1),       P((w1>>16)&255u, iv1));
            #pragma unroll
            for(int dg=0;dg<4;dg++){
                int row = kg*16 + rAdd;
                int ch = (dg*16 + cAdd)>>3;
                uint32_t r4[4];
                ldsm4t(r4, kv[c&1] + (row<<7) + ((ch ^ (row&7))<<4));
                uint32_t b0[2]={r4[0],r4[1]}, b1[2]={r4[2],r4[3]};
                mma16816(oacc[2*dg],   pa, b0);
                mma16816(oacc[2*dg+1], pa, b1);
            }
        }
    }

    int n = q0 + wid*16 + (lane>>2);
    long ro = ((long)(b*Nv) + n)*Cv + h*Dv;
    int d0 = 2*(lane&3);
    #pragma unroll
    for(int og=0;og<8;og++){
        st_bf2(z2 + ro +        og*8 + d0, qz4(oacc[og][0]), qz4(oacc[og][1]));
        st_bf2(z2 + ro + 8*Cv + og*8 + d0, qz4(oacc[og][2]), qz4(oacc[og][3]));
    }
}

// ---------------- prep: weight quant (5 tensors) + affine1, one launch ----------------
__global__ void prep_all(const float4* qw, const float4* kvw, const float4* pw,
                         const float4* f1w, const float4* f2w, const float4* x,
                         const float* a1w, const float* a1b,
                         uint2* wqkv, uint2* wpr, uint2* wf1, uint2* wf2, uint2* h1)
{
    int bx = blockIdx.x;
    if (bx >= 12288){
        int i = (bx-12288)*256 + threadIdx.x;
        float a = qz4(a1w[0]), b = qz4(a1b[0]);
        float4 v = x[i];
        float o[4] = {v.x,v.y,v.z,v.w};
        #pragma unroll
        for(int u=0;u<4;u++){ float t = qz4(o[u])*a; o[u] = qz4(qz4(t)+b); }
        __nv_bfloat162 lo = __halves2bfloat162(__float2bfloat16(o[0]), __float2bfloat16(o[1]));
        __nv_bfloat162 hi = __halves2bfloat162(__float2bfloat16(o[2]), __float2bfloat16(o[3]));
        h1[i] = make_uint2(*(uint32_t*)&lo, *(uint32_t*)&hi);
        return;
    }
    const float4* src; uint2* dst; int li;
    if      (bx < 1024){ src=qw;  dst=wqkv;          li=bx; }
    else if (bx < 3072){ src=kvw; dst=wqkv + 262144; li=bx-1024; }
    else if (bx < 4096){ src=pw;  dst=wpr;           li=bx-3072; }
    else if (bx < 8192){ src=f1w; dst=wf1;           li=bx-4096; }
    else               { src=f2w; dst=wf2;           li=bx-8192; }
    int i = li*256 + threadIdx.x;
    float4 v = src[i];
    __nv_bfloat162 lo = __halves2bfloat162(__float2bfloat16(qz7(v.x)), __float2bfloat16(qz7(v.y)));
    __nv_bfloat162 hi = __halves2bfloat162(__float2bfloat16(qz7(v.z)), __float2bfloat16(qz7(v.w)));
    dst[i] = make_uint2(*(uint32_t*)&lo, *(uint32_t*)&hi);
}

// ---------------- host launcher ----------------
extern "C" void kernel_launch(void* const* d_in, const int* in_sizes, int n_in,
                              void* d_out, int out_size)
{
    (void)in_sizes; (void)n_in; (void)out_size;
    const float* x   = (const float*)d_in[0];
    const float* qw  = (const float*)d_in[1];
    const float* kvw = (const float*)d_in[2];
    const float* pw  = (const float*)d_in[3];
    const float* pb  = (const float*)d_in[4];
    const float* f1w = (const float*)d_in[5];
    const float* f1b = (const float*)d_in[6];
    const float* f2w = (const float*)d_in[7];
    const float* f2b = (const float*)d_in[8];
    const float* a1w = (const float*)d_in[9];
    const float* a1b = (const float*)d_in[10];
    const float* a2w = (const float*)d_in[11];
    const float* a2b = (const float*)d_in[12];
    float* out = (float*)d_out;

    bf16 *wqkv,*wpr,*wf1,*wf2,*h1,*qb,*kb,*vb,*z2,*h2,*m;
    float *x1; uint8_t *sidx;
    cudaGetSymbolAddress((void**)&wqkv,g_wqkv);
    cudaGetSymbolAddress((void**)&wpr, g_wpr);
    cudaGetSymbolAddress((void**)&wf1, g_wf1);
    cudaGetSymbolAddress((void**)&wf2, g_wf2);
    cudaGetSymbolAddress((void**)&h1,  g_h1);
    cudaGetSymbolAddress((void**)&qb,  g_qb);
    cudaGetSymbolAddress((void**)&kb,  g_kb);
    cudaGetSymbolAddress((void**)&vb,  g_vb);
    cudaGetSymbolAddress((void**)&z2,  g_z2);
    cudaGetSymbolAddress((void**)&x1,  g_x1);
    cudaGetSymbolAddress((void**)&h2,  g_h2);
    cudaGetSymbolAddress((void**)&m,   g_m);
    cudaGetSymbolAddress((void**)&sidx,g_sidx);

    cudaFuncSetAttribute(gemm_mma<EpiQKV>, cudaFuncAttributeMaxDynamicSharedMemorySize, GSM);
    cudaFuncSetAttribute(gemm_mma<EpiProj>,cudaFuncAttributeMaxDynamicSharedMemorySize, GSM);
    cudaFuncSetAttribute(gemm_mma<EpiFc1>, cudaFuncAttributeMaxDynamicSharedMemorySize, GSM);
    cudaFuncSetAttribute(gemm_mma<EpiFc2>, cudaFuncAttributeMaxDynamicSharedMemorySize, GSM);
    cudaFuncSetAttribute(fattn_k,          cudaFuncAttributeMaxDynamicSharedMemorySize, FA_SM);

    // 1) weights quant + affine1 (one launch)
    prep_all<<<16384, 256>>>((const float4*)qw, (const float4*)kvw, (const float4*)pw,
                             (const float4*)f1w, (const float4*)f2w, (const float4*)x,
                             a1w, a1b,
                             (uint2*)wqkv, (uint2*)wpr, (uint2*)wf1, (uint2*)wf2, (uint2*)h1);

    // 2) fused qkv projection (Q pre-scaled x2)
    { EpiQKV e{qb,kb,vb};
      gemm_mma<EpiQKV><<<dim3(3*Cv/128, Tv/128), 256, GSM>>>(h1, wqkv, Cv, e); }

    // 3) fused attention -> z2
    fattn_k<<<dim3(Nv/128, BH), 256, FA_SM>>>(qb, kb, vb, z2, sidx);

    // 4) proj + add1 + affine2
    { EpiProj e{x, pb, a2w, a2b, x1, h2};
      gemm_mma<EpiProj><<<dim3(Cv/128,  Tv/128), 256, GSM>>>(z2, wpr, Cv, e); }
    // 5) fc1 + relu
    { EpiFc1 e{f1b, m};
      gemm_mma<EpiFc1><<<dim3(HIDv/128, Tv/128), 256, GSM>>>(h2, wf1, Cv, e); }
    // 6) fc2 + add2 -> out
    { EpiFc2 e{f2b, x1, out};
      gemm_mma<EpiFc2><<<dim3(Cv/128,  Tv/128), 256, GSM>>>(m, wf2, HIDv, e); }
}